// round 2
// baseline (speedup 1.0000x reference)
#include <cuda_runtime.h>

#define N   8192
#define NZ  256
#define NC  128
#define TPB 256

__device__ float g_r[N];   // r = tanh(x+b)
__device__ float g_z[NZ];  // z = W_rz @ r

__device__ __forceinline__ float block_reduce(float v) {
    __shared__ float sm[TPB / 32];
    int lane = threadIdx.x & 31;
    int wid  = threadIdx.x >> 5;
    #pragma unroll
    for (int o = 16; o; o >>= 1) v += __shfl_down_sync(0xffffffffu, v, o);
    if (lane == 0) sm[wid] = v;
    __syncthreads();
    if (wid == 0) {
        v = (lane < TPB / 32) ? sm[lane] : 0.0f;
        #pragma unroll
        for (int o = 16; o; o >>= 1) v += __shfl_down_sync(0xffffffffu, v, o);
    }
    return v;  // valid in thread 0
}

// partial dot of one matrix row (COLS floats, 16B-aligned) with vector v
template <int COLS>
__device__ __forceinline__ float row_dot_part(const float* __restrict__ Wrow,
                                              const float* __restrict__ v) {
    const float4* W4 = reinterpret_cast<const float4*>(Wrow);
    const float4* v4 = reinterpret_cast<const float4*>(v);
    float s = 0.0f;
    #pragma unroll
    for (int j = threadIdx.x; j < COLS / 4; j += TPB) {
        float4 w = W4[j];
        float4 x = v4[j];
        s = fmaf(w.x, x.x, s);
        s = fmaf(w.y, x.y, s);
        s = fmaf(w.z, x.z, s);
        s = fmaf(w.w, x.w, s);
    }
    return s;
}

// Kernel 1: r = tanh(x + b)
__global__ void k_rate(const float* __restrict__ x, const float* __restrict__ b) {
    int i = blockIdx.x * blockDim.x + threadIdx.x;
    if (i < N) g_r[i] = tanhf(x[i] + b[i]);
}

// Kernel 2: z = W_rz @ r   (NZ rows of length N)
__global__ void k_z(const float* __restrict__ W_rz) {
    int row = blockIdx.x;
    float s = row_dot_part<N>(W_rz + (size_t)row * N, g_r);
    s = block_reduce(s);
    if (threadIdx.x == 0) g_z[row] = s;
}

// Kernel 3: per-row fused update
// dx_i = -x_i + W_rr[i,:]@r + W_epsr[i,:]@eps + W_zr[i,:]@z + W_cr[i,:]@c
// x_new = x + 0.1*dx ; r_new = tanh(x_new + b)
// out[0:N] = x_new, out[N:2N] = r_new
__global__ void k_update(const float* __restrict__ x,
                         const float* __restrict__ b,
                         const float* __restrict__ eps,
                         const float* __restrict__ c,
                         const float* __restrict__ W_rr,
                         const float* __restrict__ W_zr,
                         const float* __restrict__ W_cr,
                         const float* __restrict__ W_epsr,
                         float* __restrict__ out) {
    int row = blockIdx.x;
    float s = row_dot_part<N>(W_rr + (size_t)row * N, g_r);
    s += row_dot_part<NZ>(W_epsr + (size_t)row * NZ, eps);
    s += row_dot_part<NZ>(W_zr + (size_t)row * NZ, g_z);
    s += row_dot_part<NC>(W_cr + (size_t)row * NC, c);
    s = block_reduce(s);
    if (threadIdx.x == 0) {
        float xi = x[row];
        float xn = xi + 0.1f * (-xi + s);   // dt=0.1, tau=1
        out[row] = xn;
        out[N + row] = tanhf(xn + b[row]);
    }
}

// Kernel 4: readouts of r_new
// rows 0..NZ-1:  z_new[row] = W_rz[row,:]@r_new ; eps_new = z_new - z_tilde
// rows NZ..NZ+NC-1: c_new = W_rc[row-NZ,:]@r_new
__global__ void k_readout(const float* __restrict__ W_rz,
                          const float* __restrict__ W_rc,
                          const float* __restrict__ z_tilde,
                          float* __restrict__ out) {
    int row = blockIdx.x;
    const float* r_new = out + N;  // written by k_update
    if (row < NZ) {
        float s = row_dot_part<N>(W_rz + (size_t)row * N, r_new);
        s = block_reduce(s);
        if (threadIdx.x == 0) {
            out[2 * N + row] = s;                          // z_new
            out[2 * N + NZ + NC + row] = s - z_tilde[row]; // eps_new
        }
    } else {
        int cr = row - NZ;
        float s = row_dot_part<N>(W_rc + (size_t)cr * N, r_new);
        s = block_reduce(s);
        if (threadIdx.x == 0) {
            out[2 * N + NZ + cr] = s;                      // c_new
        }
    }
}

extern "C" void kernel_launch(void* const* d_in, const int* in_sizes, int n_in,
                              void* d_out, int out_size) {
    const float* x       = (const float*)d_in[0];
    const float* eps     = (const float*)d_in[1];
    const float* c       = (const float*)d_in[2];
    const float* z_tilde = (const float*)d_in[3];
    const float* W_rr    = (const float*)d_in[4];
    const float* W_zr    = (const float*)d_in[5];
    const float* W_cr    = (const float*)d_in[6];
    const float* W_epsr  = (const float*)d_in[7];
    const float* W_rz    = (const float*)d_in[8];
    const float* W_rc    = (const float*)d_in[9];
    const float* b       = (const float*)d_in[10];
    float* out = (float*)d_out;

    k_rate<<<(N + TPB - 1) / TPB, TPB>>>(x, b);
    k_z<<<NZ, TPB>>>(W_rz);
    k_update<<<N, TPB>>>(x, b, eps, c, W_rr, W_zr, W_cr, W_epsr, out);
    k_readout<<<NZ + NC, TPB>>>(W_rz, W_rc, z_tilde, out);
}

// round 4
// speedup vs baseline: 1.0315x; 1.0315x over previous
#include <cuda_runtime.h>

#define N    8192
#define NZ   256
#define NC   128
#define TPB  256
#define RPB  4        // rows per block in k_update
#define SPL  4        // split-K factor for small matvecs

__device__ float g_r[N];                 // r = tanh(x+b)
__device__ float g_zpart[SPL][NZ];       // split partials of z = W_rz @ r
__device__ float g_ropart[SPL][NZ + NC]; // split partials of readout matvecs

__device__ __forceinline__ float warp_red(float v) {
    #pragma unroll
    for (int o = 16; o; o >>= 1) v += __shfl_down_sync(0xffffffffu, v, o);
    return v;
}

__device__ __forceinline__ float block_reduce(float v) {
    __shared__ float sm[TPB / 32];
    int lane = threadIdx.x & 31, wid = threadIdx.x >> 5;
    v = warp_red(v);
    if (lane == 0) sm[wid] = v;
    __syncthreads();
    if (wid == 0) {
        v = (lane < TPB / 32) ? sm[lane] : 0.0f;
        v = warp_red(v);
    }
    return v;  // valid in thread 0
}

__device__ __forceinline__ void block_reduce4(float s[RPB]) {
    __shared__ float sm[RPB][TPB / 32];
    int lane = threadIdx.x & 31, wid = threadIdx.x >> 5;
    #pragma unroll
    for (int k = 0; k < RPB; k++) {
        float v = warp_red(s[k]);
        if (lane == 0) sm[k][wid] = v;
    }
    __syncthreads();
    if (wid == 0) {
        #pragma unroll
        for (int k = 0; k < RPB; k++) {
            float v = (lane < TPB / 32) ? sm[k][lane] : 0.0f;
            s[k] = warp_red(v);   // valid in lane 0
        }
    }
}

// Kernel 1: r = tanh(x + b)
__global__ void k_rate(const float* __restrict__ x, const float* __restrict__ b) {
    int i = blockIdx.x * blockDim.x + threadIdx.x;
    if (i < N) g_r[i] = tanhf(x[i] + b[i]);
}

// Kernel 2: z partials. grid = NZ*SPL. Each block covers N/SPL cols of one row.
__global__ void k_z(const float* __restrict__ W_rz) {
    int row  = blockIdx.x >> 2;        // SPL == 4
    int part = blockIdx.x & 3;
    const int C4 = N / 4 / SPL;        // 512 float4 per part
    const float4* W4 = reinterpret_cast<const float4*>(W_rz + (size_t)row * N) + part * C4;
    const float4* r4 = reinterpret_cast<const float4*>(g_r) + part * C4;
    float s = 0.0f;
    #pragma unroll
    for (int j = threadIdx.x; j < C4; j += TPB) {
        float4 w = __ldcs(&W4[j]);
        float4 r = r4[j];
        s = fmaf(w.x, r.x, fmaf(w.y, r.y, fmaf(w.z, r.z, fmaf(w.w, r.w, s))));
    }
    s = block_reduce(s);
    if (threadIdx.x == 0) g_zpart[part][row] = s;
}

// Kernel 3: fused Euler update, RPB rows per block.
__global__ void k_update(const float* __restrict__ x,
                         const float* __restrict__ b,
                         const float* __restrict__ eps,
                         const float* __restrict__ c,
                         const float* __restrict__ W_rr,
                         const float* __restrict__ W_zr,
                         const float* __restrict__ W_cr,
                         const float* __restrict__ W_epsr,
                         float* __restrict__ out) {
    int row0 = blockIdx.x * RPB;
    const float4* r4 = reinterpret_cast<const float4*>(g_r);
    const float4* W0 = reinterpret_cast<const float4*>(W_rr + (size_t)row0 * N);
    const size_t RS = N / 4;  // row stride in float4

    float s[RPB] = {0.f, 0.f, 0.f, 0.f};
    #pragma unroll 2
    for (int j = threadIdx.x; j < N / 4; j += TPB) {
        float4 rv = r4[j];
        #pragma unroll
        for (int k = 0; k < RPB; k++) {
            float4 w = __ldcs(&W0[(size_t)k * RS + j]);
            s[k] = fmaf(w.x, rv.x, fmaf(w.y, rv.y, fmaf(w.z, rv.z, fmaf(w.w, rv.w, s[k]))));
        }
    }

    // tails: W_epsr (NZ cols) @ eps, W_zr (NZ cols) @ z, W_cr (NC cols) @ c
    if (threadIdx.x < NZ / 4) {
        int j = threadIdx.x;
        const float4* e4  = reinterpret_cast<const float4*>(eps);
        const float4* zp0 = reinterpret_cast<const float4*>(g_zpart[0]);
        const float4* zp1 = reinterpret_cast<const float4*>(g_zpart[1]);
        const float4* zp2 = reinterpret_cast<const float4*>(g_zpart[2]);
        const float4* zp3 = reinterpret_cast<const float4*>(g_zpart[3]);
        float4 ev = e4[j];
        float4 a = zp0[j], b2 = zp1[j], c2 = zp2[j], d2 = zp3[j];
        float4 zv = make_float4(a.x + b2.x + c2.x + d2.x,
                                a.y + b2.y + c2.y + d2.y,
                                a.z + b2.z + c2.z + d2.z,
                                a.w + b2.w + c2.w + d2.w);
        #pragma unroll
        for (int k = 0; k < RPB; k++) {
            const float4* We = reinterpret_cast<const float4*>(W_epsr + (size_t)(row0 + k) * NZ);
            const float4* Wz = reinterpret_cast<const float4*>(W_zr   + (size_t)(row0 + k) * NZ);
            float4 we = __ldcs(&We[j]);
            float4 wz = __ldcs(&Wz[j]);
            s[k] = fmaf(we.x, ev.x, fmaf(we.y, ev.y, fmaf(we.z, ev.z, fmaf(we.w, ev.w, s[k]))));
            s[k] = fmaf(wz.x, zv.x, fmaf(wz.y, zv.y, fmaf(wz.z, zv.z, fmaf(wz.w, zv.w, s[k]))));
        }
    }
    if (threadIdx.x < NC / 4) {
        int j = threadIdx.x;
        const float4* c4 = reinterpret_cast<const float4*>(c);
        float4 cv = c4[j];
        #pragma unroll
        for (int k = 0; k < RPB; k++) {
            const float4* Wc = reinterpret_cast<const float4*>(W_cr + (size_t)(row0 + k) * NC);
            float4 wc = __ldcs(&Wc[j]);
            s[k] = fmaf(wc.x, cv.x, fmaf(wc.y, cv.y, fmaf(wc.z, cv.z, fmaf(wc.w, cv.w, s[k]))));
        }
    }

    block_reduce4(s);
    if (threadIdx.x == 0) {
        #pragma unroll
        for (int k = 0; k < RPB; k++) {
            int row = row0 + k;
            float xi = x[row];
            float xn = xi + 0.1f * (-xi + s[k]);   // dt=0.1, tau=1
            out[row] = xn;
            out[N + row] = tanhf(xn + b[row]);
        }
    }
}

// Kernel 4: readout partials on r_new. grid = (NZ+NC)*SPL.
__global__ void k_readout(const float* __restrict__ W_rz,
                          const float* __restrict__ W_rc,
                          const float* __restrict__ out) {
    int row  = blockIdx.x >> 2;
    int part = blockIdx.x & 3;
    const int C4 = N / 4 / SPL;
    const float* Wrow = (row < NZ) ? (W_rz + (size_t)row * N)
                                   : (W_rc + (size_t)(row - NZ) * N);
    const float4* W4 = reinterpret_cast<const float4*>(Wrow) + part * C4;
    const float4* r4 = reinterpret_cast<const float4*>(out + N) + part * C4;  // r_new
    float s = 0.0f;
    #pragma unroll
    for (int j = threadIdx.x; j < C4; j += TPB) {
        float4 w = __ldcs(&W4[j]);
        float4 r = r4[j];
        s = fmaf(w.x, r.x, fmaf(w.y, r.y, fmaf(w.z, r.z, fmaf(w.w, r.w, s))));
    }
    s = block_reduce(s);
    if (threadIdx.x == 0) g_ropart[part][row] = s;
}

// Kernel 5: combine readout partials, write z_new, c_new, eps_new.
__global__ void k_final(const float* __restrict__ z_tilde, float* __restrict__ out) {
    int i = threadIdx.x;  // 0..NZ+NC-1
    float s = g_ropart[0][i] + g_ropart[1][i] + g_ropart[2][i] + g_ropart[3][i];
    if (i < NZ) {
        out[2 * N + i] = s;                           // z_new
        out[2 * N + NZ + NC + i] = s - z_tilde[i];    // eps_new
    } else {
        out[2 * N + NZ + (i - NZ)] = s;               // c_new
    }
}

extern "C" void kernel_launch(void* const* d_in, const int* in_sizes, int n_in,
                              void* d_out, int out_size) {
    const float* x       = (const float*)d_in[0];
    const float* eps     = (const float*)d_in[1];
    const float* c       = (const float*)d_in[2];
    const float* z_tilde = (const float*)d_in[3];
    const float* W_rr    = (const float*)d_in[4];
    const float* W_zr    = (const float*)d_in[5];
    const float* W_cr    = (const float*)d_in[6];
    const float* W_epsr  = (const float*)d_in[7];
    const float* W_rz    = (const float*)d_in[8];
    const float* W_rc    = (const float*)d_in[9];
    const float* b       = (const float*)d_in[10];
    float* out = (float*)d_out;

    k_rate<<<(N + TPB - 1) / TPB, TPB>>>(x, b);
    k_z<<<NZ * SPL, TPB>>>(W_rz);
    k_update<<<N / RPB, TPB>>>(x, b, eps, c, W_rr, W_zr, W_cr, W_epsr, out);
    k_readout<<<(NZ + NC) * SPL, TPB>>>(W_rz, W_rc, out);
    k_final<<<1, NZ + NC>>>(z_tilde, out);
}